// round 1
// baseline (speedup 1.0000x reference)
#include <cuda_runtime.h>
#include <cuda_bf16.h>

// ---------------------------------------------------------------------------
// Static problem geometry (grids are compile-time constants in the reference)
//   s0: t=8,  32x32  -> tokens [0,     8192)   pe2d rows [0,    1024)
//   s1: t=16, 16x16  -> tokens [8192,  12288)  pe2d rows [1024, 1280)
//   s2: t=4,  48x48  -> tokens [12288, 21504)  pe2d rows [1280, 3584)
//   s3: t=1,  64x64  -> tokens [21504, 25600)  pe = weight row directly
// ---------------------------------------------------------------------------
#define DIM      1280
#define D4       320           // DIM / 4
#define NROWS_W  96            // 32 + 16 + 48 resize-output rows
#define PE_ROWS  3584          // 1024 + 256 + 2304
#define TOKENS   25600

// Scratch (module-static device memory: allowed, no runtime allocation)
__device__ float g_W[NROWS_W * 64];     // normalized bicubic weight rows
__device__ int   g_lo[NROWS_W];
__device__ int   g_hi[NROWS_W];
__device__ float g_tmpW[64 * NROWS_W * DIM];   // [i][c][d]  ~31.5 MB
__device__ float g_pe2d[PE_ROWS * DIM];        // ~18.3 MB

// Keys cubic, a = -0.5 (matches jax _fill_keys_cubic_kernel)
__device__ __forceinline__ double keys_cubic(double x) {
    if (x >= 2.0) return 0.0;
    if (x >= 1.0) return ((-0.5 * x + 2.5) * x - 4.0) * x + 2.0;
    return ((1.5 * x - 2.5) * x) * x + 1.0;
}

// ---------------------------------------------------------------------------
// Kernel 0: build the three resize weight matrices (rows 0..31: 64->32,
// 32..47: 64->16, 48..95: 64->48), jax-antialiased, column-normalized.
// ---------------------------------------------------------------------------
__global__ void init_weights_kernel() {
    int o = threadIdx.x;
    if (o >= NROWS_W) return;
    int outsz, base;
    if (o < 32)      { outsz = 32; base = 0;  }
    else if (o < 48) { outsz = 16; base = 32; }
    else             { outsz = 48; base = 48; }
    int r = o - base;

    double inv_scale    = 64.0 / (double)outsz;
    double kernel_scale = inv_scale;                 // antialias (inv_scale > 1)
    double f = ((double)r + 0.5) * inv_scale - 0.5;  // sample position

    double wsum = 0.0;
    int lo = 64, hi = -1;
    #pragma unroll 1
    for (int i = 0; i < 64; i++) {
        double xx = fabs(f - (double)i) / kernel_scale;
        double w  = keys_cubic(xx);
        wsum += w;
        if (xx < 2.0) { if (i < lo) lo = i; if (i > hi) hi = i; }
    }
    double inv_sum = 1.0 / wsum;
    #pragma unroll 1
    for (int i = 0; i < 64; i++) {
        double xx = fabs(f - (double)i) / kernel_scale;
        g_W[o * 64 + i] = (float)(keys_cubic(xx) * inv_sum);
    }
    g_lo[o] = lo;
    g_hi[o] = hi;
}

// ---------------------------------------------------------------------------
// Kernel 1 (W-pass): tmpW[i][c][d] = sum_j Ww[c][j] * weight[i][j][d]
// One block per (input row i, 128-float d-chunk). Stage all 64 j values of
// this chunk in smem (weight read exactly once from DRAM), then emit all 96
// resized columns using the sparse tap windows.
// ---------------------------------------------------------------------------
__global__ __launch_bounds__(128) void passW_kernel(const float* __restrict__ weight) {
    int i  = blockIdx.x;       // 0..63
    int d0 = blockIdx.y * 128; // 0..9 chunks
    int tid = threadIdx.x;     // 0..127

    __shared__ float s[64 * 128];
    const float* wrow = weight + (size_t)(i * 64) * DIM + d0;
    #pragma unroll 8
    for (int j = 0; j < 64; j++)
        s[j * 128 + tid] = wrow[(size_t)j * DIM + tid];
    __syncthreads();

    float* outp = g_tmpW + (size_t)i * NROWS_W * DIM + d0 + tid;
    #pragma unroll 1
    for (int c = 0; c < NROWS_W; c++) {
        int lo = g_lo[c], hi = g_hi[c];
        const float* wr = g_W + c * 64;
        float acc = 0.f;
        for (int j = lo; j <= hi; j++)
            acc = fmaf(wr[j], s[j * 128 + tid], acc);
        outp[(size_t)c * DIM] = acc;
    }
}

// ---------------------------------------------------------------------------
// Kernel 2 (H-pass): pe2d[row(s,r,c)][d] = sum_i Wh[r][i] * tmpW[i][c][d]
// One block per (global column c, d-chunk). Stage the 64 i values in smem,
// then emit every output row of c's sample.
// ---------------------------------------------------------------------------
__global__ __launch_bounds__(128) void passH_kernel() {
    int c  = blockIdx.x;       // 0..95
    int d0 = blockIdx.y * 128;
    int tid = threadIdx.x;

    __shared__ float s[64 * 128];
    const float* src = g_tmpW + (size_t)c * DIM + d0 + tid;
    #pragma unroll 8
    for (int i = 0; i < 64; i++)
        s[i * 128 + tid] = src[(size_t)i * NROWS_W * DIM];
    __syncthreads();

    int rbase, rcnt, ws, clocal, rowoff;
    if (c < 32)      { rbase = 0;  rcnt = 32; ws = 32; clocal = c;      rowoff = 0;    }
    else if (c < 48) { rbase = 32; rcnt = 16; ws = 16; clocal = c - 32; rowoff = 1024; }
    else             { rbase = 48; rcnt = 48; ws = 48; clocal = c - 48; rowoff = 1280; }

    #pragma unroll 1
    for (int r = 0; r < rcnt; r++) {
        int g = rbase + r;
        int lo = g_lo[g], hi = g_hi[g];
        const float* wr = g_W + g * 64;
        float acc = 0.f;
        for (int i = lo; i <= hi; i++)
            acc = fmaf(wr[i], s[i * 128 + tid], acc);
        g_pe2d[(size_t)(rowoff + r * ws + clocal) * DIM + d0 + tid] = acc;
    }
}

// ---------------------------------------------------------------------------
// Kernel 3: out = x + pe2d[row(tok)] (+ time_weight[frame] when t > 1)
// Pure streaming float4 pass; pe2d/time_weight hit L2/L1.
// ---------------------------------------------------------------------------
__global__ __launch_bounds__(256) void add_kernel(const float4* __restrict__ x,
                                                  const float4* __restrict__ weight,
                                                  const float4* __restrict__ tw,
                                                  float4* __restrict__ out) {
    long idx = (long)blockIdx.x * blockDim.x + threadIdx.x;
    if (idx >= (long)TOKENS * D4) return;
    int tok = (int)(idx / D4);
    int d4  = (int)(idx - (long)tok * D4);

    const float4* pe;
    int frame = -1;
    if (tok < 8192) {                       // s0: t=8, 32x32
        frame = tok >> 10;
        pe = (const float4*)g_pe2d + (size_t)(tok & 1023) * D4;
    } else if (tok < 12288) {               // s1: t=16, 16x16
        int u = tok - 8192;
        frame = u >> 8;
        pe = (const float4*)g_pe2d + (size_t)(1024 + (u & 255)) * D4;
    } else if (tok < 21504) {               // s2: t=4, 48x48
        int u = tok - 12288;
        frame = u / 2304;
        pe = (const float4*)g_pe2d + (size_t)(1280 + (u - frame * 2304)) * D4;
    } else {                                // s3: t=1, identity 64x64
        int u = tok - 21504;
        pe = weight + (size_t)u * D4;
    }

    float4 a = x[idx];
    float4 b = pe[d4];
    float4 r;
    r.x = a.x + b.x; r.y = a.y + b.y; r.z = a.z + b.z; r.w = a.w + b.w;
    if (frame >= 0) {
        float4 t = tw[(size_t)frame * D4 + d4];
        r.x += t.x; r.y += t.y; r.z += t.z; r.w += t.w;
    }
    out[idx] = r;
}

// ---------------------------------------------------------------------------
extern "C" void kernel_launch(void* const* d_in, const int* in_sizes, int n_in,
                              void* d_out, int out_size) {
    const float* x      = (const float*)d_in[0];   // [25600*1280]
    const float* weight = (const float*)d_in[1];   // [64*64*1280]
    const float* tw     = (const float*)d_in[2];   // [16*1280]
    // d_in[3] = grid_thws (static; unused)
    float* out = (float*)d_out;

    init_weights_kernel<<<1, 128>>>();
    passW_kernel<<<dim3(64, 10), 128>>>(weight);
    passH_kernel<<<dim3(96, 10), 128>>>();

    long total4 = (long)TOKENS * D4;                 // 8,192,000
    int blocks = (int)((total4 + 255) / 256);        // 32,000
    add_kernel<<<blocks, 256>>>((const float4*)x, (const float4*)weight,
                                (const float4*)tw, (float4*)out);
}

// round 5
// speedup vs baseline: 1.9852x; 1.9852x over previous
#include <cuda_runtime.h>
#include <cuda_bf16.h>

// ---------------------------------------------------------------------------
// Static geometry:
//   s0: t=8,  32x32 -> tokens [0,8192)      pe2d rows [0,1024)
//   s1: t=16, 16x16 -> tokens [8192,12288)  pe2d rows [1024,1280)
//   s2: t=4,  48x48 -> tokens [12288,21504) pe2d rows [1280,3584)
//   s3: t=1,  64x64 -> tokens [21504,25600) pe = weight rows directly
// Resize-output rows (both axes, h==w): 0..31: 64->32, 32..47: 64->16, 48..95: 64->48
// ---------------------------------------------------------------------------
#define DIM      1280
#define D4       320
#define NROWS_W  96
#define PE_ROWS  3584
#define TOKENS   25600

__device__ float g_Wp[NROWS_W * 16];    // zero-padded 16-tap windows (normalized)
__device__ int   g_start[NROWS_W];      // window start index into 0..63
__device__ float g_tmpW[64 * NROWS_W * DIM];   // [i][c][d]
__device__ float g_pe2d[PE_ROWS * DIM];

// Keys cubic a=-0.5, argument pre-scaled (matches jax _fill_keys_cubic_kernel)
__device__ __forceinline__ double keys_cubic(double x) {
    if (x >= 2.0) return 0.0;
    if (x >= 1.0) return ((-0.5 * x + 2.5) * x - 4.0) * x + 2.0;
    return ((1.5 * x - 2.5) * x) * x + 1.0;
}

// ---------------------------------------------------------------------------
// Kernel 0: padded windowed bicubic weights. No fp64 division in loops.
// ---------------------------------------------------------------------------
__global__ void init_weights_kernel() {
    int o = threadIdx.x;
    if (o >= NROWS_W) return;
    int outsz, base;
    if (o < 32)      { outsz = 32; base = 0;  }
    else if (o < 48) { outsz = 16; base = 32; }
    else             { outsz = 48; base = 48; }
    int r = o - base;

    double inv_scale = 64.0 / (double)outsz;         // == kernel_scale (antialias)
    double ks_inv    = (double)outsz * (1.0 / 64.0); // 1/kernel_scale
    double f = ((double)r + 0.5) * inv_scale - 0.5;

    int lo = (int)ceil(f - 2.0 * inv_scale);
    int start = lo < 0 ? 0 : (lo > 48 ? 48 : lo);

    double wv[16];
    double wsum = 0.0;
    #pragma unroll
    for (int k = 0; k < 16; k++) {
        int i = start + k;
        double w = keys_cubic(fabs(f - (double)i) * ks_inv);
        wv[k] = w;
        wsum += w;
    }
    double inv_sum = 1.0 / wsum;
    #pragma unroll
    for (int k = 0; k < 16; k++)
        g_Wp[o * 16 + k] = (float)(wv[k] * inv_sum);
    g_start[o] = start;
}

// ---------------------------------------------------------------------------
// Kernel 1 (W-pass): tmpW[i][c][d] = sum_k Wp[c][k] * weight[i][start_c+k][d]
// Block = (input row i, 128-float d-chunk). weight read once from DRAM.
// ---------------------------------------------------------------------------
__global__ __launch_bounds__(128) void passW_kernel(const float* __restrict__ weight) {
    int i  = blockIdx.x;
    int d0 = blockIdx.y * 128;
    int tid = threadIdx.x;

    __shared__ float s[64 * 128];
    __shared__ float sw[NROWS_W * 16];
    __shared__ int   sst[NROWS_W];

    const float* wrow = weight + (size_t)(i * 64) * DIM + d0;
    #pragma unroll
    for (int j = 0; j < 64; j++)
        s[j * 128 + tid] = wrow[(size_t)j * DIM + tid];
    for (int k = tid; k < NROWS_W * 16; k += 128) sw[k] = g_Wp[k];
    if (tid < NROWS_W) sst[tid] = g_start[tid];
    __syncthreads();

    float* outp = g_tmpW + (size_t)i * NROWS_W * DIM + d0 + tid;
    #pragma unroll 2
    for (int c = 0; c < NROWS_W; c++) {
        int st = sst[c];
        const float* w = &sw[c * 16];
        const float* sp = &s[st * 128 + tid];
        float acc = 0.f;
        #pragma unroll
        for (int k = 0; k < 16; k++)
            acc = fmaf(w[k], sp[k * 128], acc);
        outp[(size_t)c * DIM] = acc;
    }
}

// ---------------------------------------------------------------------------
// Kernel 2 (H-pass): pe2d[row(s,r,c)][d] = sum_k Wp[r][k] * tmpW[start_r+k][c][d]
// Block = (global resized column c, d-chunk).
// ---------------------------------------------------------------------------
__global__ __launch_bounds__(128) void passH_kernel() {
    int c  = blockIdx.x;
    int d0 = blockIdx.y * 128;
    int tid = threadIdx.x;

    __shared__ float s[64 * 128];
    __shared__ float sw[NROWS_W * 16];
    __shared__ int   sst[NROWS_W];

    const float* src = g_tmpW + (size_t)c * DIM + d0 + tid;
    #pragma unroll
    for (int i = 0; i < 64; i++)
        s[i * 128 + tid] = src[(size_t)i * NROWS_W * DIM];
    for (int k = tid; k < NROWS_W * 16; k += 128) sw[k] = g_Wp[k];
    if (tid < NROWS_W) sst[tid] = g_start[tid];
    __syncthreads();

    int rbase, rcnt, ws, clocal, rowoff;
    if (c < 32)      { rbase = 0;  rcnt = 32; ws = 32; clocal = c;      rowoff = 0;    }
    else if (c < 48) { rbase = 32; rcnt = 16; ws = 16; clocal = c - 32; rowoff = 1024; }
    else             { rbase = 48; rcnt = 48; ws = 48; clocal = c - 48; rowoff = 1280; }

    float* outbase = g_pe2d + (size_t)(rowoff + clocal) * DIM + d0 + tid;
    #pragma unroll 2
    for (int r = 0; r < rcnt; r++) {
        int g = rbase + r;
        int st = sst[g];
        const float* w = &sw[g * 16];
        const float* sp = &s[st * 128 + tid];
        float acc = 0.f;
        #pragma unroll
        for (int k = 0; k < 16; k++)
            acc = fmaf(w[k], sp[k * 128], acc);
        outbase[(size_t)(r * ws) * DIM] = acc;
    }
}

// ---------------------------------------------------------------------------
// Kernel 3: out = x + pe(+tw). One block per token; 320 threads = one row.
// No 64-bit division; token decode is block-uniform.
// ---------------------------------------------------------------------------
__global__ __launch_bounds__(320) void add_kernel(const float4* __restrict__ x,
                                                  const float4* __restrict__ weight,
                                                  const float4* __restrict__ tw,
                                                  float4* __restrict__ out) {
    int tok = blockIdx.x;
    if (tok >= TOKENS) return;
    int d4  = threadIdx.x;

    const float4* pe;
    int frame = -1;
    if (tok < 8192) {                       // s0: t=8, 32x32
        frame = tok >> 10;
        pe = (const float4*)g_pe2d + (size_t)(tok & 1023) * D4;
    } else if (tok < 12288) {               // s1: t=16, 16x16
        int u = tok - 8192;
        frame = u >> 8;
        pe = (const float4*)g_pe2d + (size_t)(1024 + (u & 255)) * D4;
    } else if (tok < 21504) {               // s2: t=4, 48x48
        int u = tok - 12288;
        frame = u / 2304;
        pe = (const float4*)g_pe2d + (size_t)(1280 + (u - frame * 2304)) * D4;
    } else {                                // s3: t=1, identity 64x64
        pe = weight + (size_t)(tok - 21504) * D4;
    }

    size_t idx = (size_t)tok * D4 + d4;
    float4 a = x[idx];
    float4 b = pe[d4];
    float4 r;
    r.x = a.x + b.x; r.y = a.y + b.y; r.z = a.z + b.z; r.w = a.w + b.w;
    if (frame >= 0) {
        float4 t = tw[(size_t)frame * D4 + d4];
        r.x += t.x; r.y += t.y; r.z += t.z; r.w += t.w;
    }
    out[idx] = r;
}

// ---------------------------------------------------------------------------
extern "C" void kernel_launch(void* const* d_in, const int* in_sizes, int n_in,
                              void* d_out, int out_size) {
    const float* x      = (const float*)d_in[0];
    const float* weight = (const float*)d_in[1];
    const float* tw     = (const float*)d_in[2];
    float* out = (float*)d_out;

    init_weights_kernel<<<1, 128>>>();
    passW_kernel<<<dim3(64, 10), 128>>>(weight);
    passH_kernel<<<dim3(96, 10), 128>>>();
    add_kernel<<<TOKENS, 320>>>((const float4*)x, (const float4*)weight,
                                (const float4*)tw, (float4*)out);
}

// round 8
// speedup vs baseline: 2.8417x; 1.4314x over previous
#include <cuda_runtime.h>
#include <cuda_bf16.h>

// ---------------------------------------------------------------------------
// Static geometry:
//   s0: t=8,  32x32 -> tokens [0,8192)      pe2d rows [0,1024)
//   s1: t=16, 16x16 -> tokens [8192,12288)  pe2d rows [1024,1280)
//   s2: t=4,  48x48 -> tokens [12288,21504) pe2d rows [1280,3584)
//   s3: t=1,  64x64 -> tokens [21504,25600) pe = weight rows directly
// Resize rows (axes symmetric, h==w): g 0..31: 64->32, 32..47: 64->16, 48..95: 64->48
// ---------------------------------------------------------------------------
#define DIM      1280
#define D4       320
#define NROWS_W  96
#define PE_ROWS  3584
#define TOKENS   25600

__device__ float g_Wp[NROWS_W * 16];           // padded 16-tap windows (normalized)
__device__ float g_tmpW[64 * NROWS_W * DIM];   // [i][c][d]
__device__ float g_pe2d[PE_ROWS * DIM];

// ---------------------------------------------------------------------------
// Compile-time tap-window geometry (integer-exact; matches ceil(f - 2*inv_scale))
//   outsz=32: inv=2,   f=2r+0.5   -> lo = 2r-3            width 8
//   outsz=16: inv=4,   f=4r+1.5   -> lo = 4r-6            width 16
//   outsz=48: inv=4/3, f=(8r+1)/6 -> lo = ceil((8r-15)/6) width 6
// start clamped to [0, 64-width]; taps outside true support carry weight 0.
// ---------------------------------------------------------------------------
__host__ __device__ constexpr int cdiv_ceil(int n, int d) {
    return (n >= 0) ? (n + d - 1) / d : -((-n) / d);
}
__host__ __device__ constexpr int iclamp(int v, int lo, int hi) {
    return v < lo ? lo : (v > hi ? hi : v);
}
__host__ __device__ constexpr int rowStart(int g) {
    return (g < 32) ? iclamp(2 * g - 3, 0, 56)
         : (g < 48) ? iclamp(4 * (g - 32) - 6, 0, 48)
                    : iclamp(cdiv_ceil(8 * (g - 48) - 15, 6), 0, 58);
}
__host__ __device__ constexpr int rowWidth(int g) {
    return (g < 32) ? 8 : (g < 48) ? 16 : 6;
}

// Keys cubic a=-0.5, pre-scaled argument (matches jax _fill_keys_cubic_kernel)
__device__ __forceinline__ double keys_cubic(double x) {
    if (x >= 2.0) return 0.0;
    if (x >= 1.0) return ((-0.5 * x + 2.5) * x - 4.0) * x + 2.0;
    return ((1.5 * x - 2.5) * x) * x + 1.0;
}

// ---------------------------------------------------------------------------
// Kernel 0: windowed, column-normalized bicubic weights (fp64, antialiased).
// CRITICAL: taps whose source index falls outside [0,64) are masked to zero
// BEFORE the normalization sum — the reference normalizes over the valid
// column only. (R7 bug: clamped boundary rows leaked i>=64 taps into wsum.)
// ---------------------------------------------------------------------------
__global__ void init_weights_kernel() {
    int o = threadIdx.x;
    if (o >= NROWS_W) return;
    int outsz, base;
    if (o < 32)      { outsz = 32; base = 0;  }
    else if (o < 48) { outsz = 16; base = 32; }
    else             { outsz = 48; base = 48; }
    int r = o - base;

    double inv_scale = 64.0 / (double)outsz;         // == kernel_scale (antialias)
    double ks_inv    = (double)outsz * (1.0 / 64.0); // 1/kernel_scale
    double f = ((double)r + 0.5) * inv_scale - 0.5;
    int start = rowStart(o);

    double wv[16];
    double wsum = 0.0;
    #pragma unroll
    for (int k = 0; k < 16; k++) {
        int i = start + k;
        double w = (i < 64) ? keys_cubic(fabs(f - (double)i) * ks_inv) : 0.0;
        wv[k] = w;
        wsum += w;
    }
    double inv_sum = 1.0 / wsum;
    #pragma unroll
    for (int k = 0; k < 16; k++)
        g_Wp[o * 16 + k] = (float)(wv[k] * inv_sum);
}

// ---------------------------------------------------------------------------
// Template-unrolled column emitters: data in REGISTERS (compile-time indices),
// weights broadcast from smem. C++14-safe recursion.
// ---------------------------------------------------------------------------
template<int C>
struct WCol {
    static __device__ __forceinline__ void run(const float (&v)[64],
                                               const float* __restrict__ sw,
                                               float* __restrict__ outp) {
        constexpr int st = rowStart(C);
        constexpr int wd = rowWidth(C);
        float acc = 0.f;
        #pragma unroll
        for (int k = 0; k < wd; k++)
            acc = fmaf(sw[C * 16 + k], v[st + k], acc);
        outp[(size_t)C * DIM] = acc;
        WCol<C + 1>::run(v, sw, outp);
    }
};
template<>
struct WCol<NROWS_W> {
    static __device__ __forceinline__ void run(const float (&)[64],
                                               const float*, float*) {}
};

template<int GBASE, int RCNT, int WS, int R, bool Done>
struct HRow {
    static __device__ __forceinline__ void run(const float (&v)[64],
                                               const float* __restrict__ sw,
                                               float* __restrict__ outp) {
        constexpr int g  = GBASE + R;
        constexpr int st = rowStart(g);
        constexpr int wd = rowWidth(g);
        float acc = 0.f;
        #pragma unroll
        for (int k = 0; k < wd; k++)
            acc = fmaf(sw[g * 16 + k], v[st + k], acc);
        outp[(size_t)(R * WS) * DIM] = acc;
        HRow<GBASE, RCNT, WS, R + 1, (R + 1 >= RCNT)>::run(v, sw, outp);
    }
};
template<int GBASE, int RCNT, int WS, int R>
struct HRow<GBASE, RCNT, WS, R, true> {
    static __device__ __forceinline__ void run(const float (&)[64],
                                               const float*, float*) {}
};

// ---------------------------------------------------------------------------
// Kernel 1 (W-pass): tmpW[i][c][d] = sum_k Wp[c][k] * weight[i][st_c+k][d]
// Block = (input row i, 128-float d-chunk). Data register-resident.
// ---------------------------------------------------------------------------
__global__ __launch_bounds__(128) void passW_kernel(const float* __restrict__ weight) {
    int i  = blockIdx.x;
    int d0 = blockIdx.y * 128;
    int tid = threadIdx.x;

    __shared__ float sw[NROWS_W * 16];
    for (int k = tid; k < NROWS_W * 16; k += 128) sw[k] = g_Wp[k];

    float v[64];
    const float* wrow = weight + (size_t)(i * 64) * DIM + d0 + tid;
    #pragma unroll
    for (int j = 0; j < 64; j++)
        v[j] = wrow[(size_t)j * DIM];
    __syncthreads();

    float* outp = g_tmpW + (size_t)i * NROWS_W * DIM + d0 + tid;
    WCol<0>::run(v, sw, outp);
}

// ---------------------------------------------------------------------------
// Kernel 2 (H-pass): pe2d[row(s,r,c)][d] = sum_k Wp[r][k] * tmpW[st_r+k][c][d]
// Block = (global resized column c, d-chunk). Data register-resident.
// ---------------------------------------------------------------------------
__global__ __launch_bounds__(128) void passH_kernel() {
    int c  = blockIdx.x;
    int d0 = blockIdx.y * 128;
    int tid = threadIdx.x;

    __shared__ float sw[NROWS_W * 16];
    for (int k = tid; k < NROWS_W * 16; k += 128) sw[k] = g_Wp[k];

    float v[64];
    const float* src = g_tmpW + (size_t)c * DIM + d0 + tid;
    #pragma unroll
    for (int i = 0; i < 64; i++)
        v[i] = src[(size_t)i * (NROWS_W * DIM)];
    __syncthreads();

    if (c < 32) {
        float* outp = g_pe2d + (size_t)c * DIM + d0 + tid;
        HRow<0, 32, 32, 0, false>::run(v, sw, outp);
    } else if (c < 48) {
        float* outp = g_pe2d + (size_t)(1024 + (c - 32)) * DIM + d0 + tid;
        HRow<32, 16, 16, 0, false>::run(v, sw, outp);
    } else {
        float* outp = g_pe2d + (size_t)(1280 + (c - 48)) * DIM + d0 + tid;
        HRow<48, 48, 48, 0, false>::run(v, sw, outp);
    }
}

// ---------------------------------------------------------------------------
// Kernel 3: out = x + pe(+tw). One block per token; 320 threads = one row.
// x/out use streaming hints so pe2d/weight stay L2-resident.
// ---------------------------------------------------------------------------
__global__ __launch_bounds__(320) void add_kernel(const float4* __restrict__ x,
                                                  const float4* __restrict__ weight,
                                                  const float4* __restrict__ tw,
                                                  float4* __restrict__ out) {
    int tok = blockIdx.x;
    int d4  = threadIdx.x;

    const float4* pe;
    int frame = -1;
    if (tok < 8192) {                       // s0: t=8, 32x32
        frame = tok >> 10;
        pe = (const float4*)g_pe2d + (size_t)(tok & 1023) * D4;
    } else if (tok < 12288) {               // s1: t=16, 16x16
        int u = tok - 8192;
        frame = u >> 8;
        pe = (const float4*)g_pe2d + (size_t)(1024 + (u & 255)) * D4;
    } else if (tok < 21504) {               // s2: t=4, 48x48
        int u = tok - 12288;
        frame = u / 2304;
        pe = (const float4*)g_pe2d + (size_t)(1280 + (u - frame * 2304)) * D4;
    } else {                                // s3: t=1, identity 64x64
        pe = weight + (size_t)(tok - 21504) * D4;
    }

    size_t idx = (size_t)tok * D4 + d4;
    float4 a = __ldcs(&x[idx]);             // streaming: don't pollute L2
    float4 b = pe[d4];
    float4 r;
    r.x = a.x + b.x; r.y = a.y + b.y; r.z = a.z + b.z; r.w = a.w + b.w;
    if (frame >= 0) {
        float4 t = tw[(size_t)frame * D4 + d4];
        r.x += t.x; r.y += t.y; r.z += t.z; r.w += t.w;
    }
    __stcs(&out[idx], r);                   // streaming store
}

// ---------------------------------------------------------------------------
extern "C" void kernel_launch(void* const* d_in, const int* in_sizes, int n_in,
                              void* d_out, int out_size) {
    const float* x      = (const float*)d_in[0];
    const float* weight = (const float*)d_in[1];
    const float* tw     = (const float*)d_in[2];
    float* out = (float*)d_out;

    init_weights_kernel<<<1, 128>>>();
    passW_kernel<<<dim3(64, 10), 128>>>(weight);
    passH_kernel<<<dim3(96, 10), 128>>>();
    add_kernel<<<TOKENS, 320>>>((const float4*)x, (const float4*)weight,
                                (const float4*)tw, (float4*)out);
}

// round 11
// speedup vs baseline: 3.7346x; 1.3142x over previous
#include <cuda_runtime.h>
#include <cuda_bf16.h>

// ---------------------------------------------------------------------------
// Static geometry:
//   s0: t=8,  32x32 -> tokens [0,8192)      pe2d rows [0,1024)
//   s1: t=16, 16x16 -> tokens [8192,12288)  pe2d rows [1024,1280)
//   s2: t=4,  48x48 -> tokens [12288,21504) pe2d rows [1280,3584)
//   s3: t=1,  64x64 -> tokens [21504,25600) pe = weight rows directly
// Resize rows (axes symmetric, h==w): g 0..31: 64->32, 32..47: 64->16, 48..95: 64->48
// ---------------------------------------------------------------------------
#define DIM      1280
#define D4       320
#define NROWS_W  96
#define PE_ROWS  3584
#define TOKENS   25600
#define TPB      4          // tokens per add-block (all boundaries divisible by 4)

__device__ float g_tmpW[64 * NROWS_W * DIM];   // [i][c][d]
__device__ float g_pe2d[PE_ROWS * DIM];

// ---------------------------------------------------------------------------
// Compile-time tap-window geometry (integer-exact; matches ceil(f - 2*inv_scale))
//   outsz=32: inv=2,   f=2r+0.5   -> lo = 2r-3            width 8
//   outsz=16: inv=4,   f=4r+1.5   -> lo = 4r-6            width 16
//   outsz=48: inv=4/3, f=(8r+1)/6 -> lo = ceil((8r-15)/6) width 6
// start clamped to [0, 64-width]; taps outside [0,64) masked BEFORE wsum.
// ---------------------------------------------------------------------------
__host__ __device__ constexpr int cdiv_ceil(int n, int d) {
    return (n >= 0) ? (n + d - 1) / d : -((-n) / d);
}
__host__ __device__ constexpr int iclamp(int v, int lo, int hi) {
    return v < lo ? lo : (v > hi ? hi : v);
}
__host__ __device__ constexpr int rowStart(int g) {
    return (g < 32) ? iclamp(2 * g - 3, 0, 56)
         : (g < 48) ? iclamp(4 * (g - 32) - 6, 0, 48)
                    : iclamp(cdiv_ceil(8 * (g - 48) - 15, 6), 0, 58);
}
__host__ __device__ constexpr int rowWidth(int g) {
    return (g < 32) ? 8 : (g < 48) ? 16 : 6;
}

// ---------------------------------------------------------------------------
// Compile-time weight table: exact fp64 Keys-cubic (a=-0.5), antialiased,
// column-normalized over valid taps only. Same math as the R8 init kernel,
// evaluated by the host compiler. Weights land as FFMA immediates.
// ---------------------------------------------------------------------------
constexpr double c_abs(double x) { return x < 0.0 ? -x : x; }
constexpr double keys_cubic_c(double x) {
    return (x >= 2.0) ? 0.0
         : (x >= 1.0) ? ((-0.5 * x + 2.5) * x - 4.0) * x + 2.0
                      : ((1.5 * x - 2.5) * x) * x + 1.0;
}

struct WTable { float w[NROWS_W][16]; };

constexpr WTable make_wtable() {
    WTable t{};
    for (int o = 0; o < NROWS_W; o++) {
        int outsz = (o < 32) ? 32 : (o < 48) ? 16 : 48;
        int base  = (o < 32) ? 0  : (o < 48) ? 32 : 48;
        int r = o - base;
        double inv_scale = 64.0 / (double)outsz;          // == kernel_scale
        double ks_inv    = (double)outsz * (1.0 / 64.0);  // 1/kernel_scale
        double f = ((double)r + 0.5) * inv_scale - 0.5;
        int start = rowStart(o);
        double wv[16] = {};
        double wsum = 0.0;
        for (int k = 0; k < 16; k++) {
            int i = start + k;
            double w = (i < 64) ? keys_cubic_c(c_abs(f - (double)i) * ks_inv) : 0.0;
            wv[k] = w;
            wsum += w;
        }
        for (int k = 0; k < 16; k++)
            t.w[o][k] = (float)(wv[k] / wsum);
    }
    return t;
}

constexpr WTable WT = make_wtable();

// ---------------------------------------------------------------------------
// Template-unrolled emitters: data in registers (compile-time indices),
// weights as compile-time immediates. C++14-safe recursion.
// ---------------------------------------------------------------------------
template<int G, int K, bool Done>
struct Tap {
    static __device__ __forceinline__ float run(const float (&v)[64], float acc) {
        constexpr float wk = WT.w[G][K];
        constexpr int   st = rowStart(G);
        acc = fmaf(wk, v[st + K], acc);
        return Tap<G, K + 1, (K + 1 >= rowWidth(G))>::run(v, acc);
    }
};
template<int G, int K>
struct Tap<G, K, true> {
    static __device__ __forceinline__ float run(const float (&)[64], float acc) { return acc; }
};

template<int C, bool Done>
struct WCol {
    static __device__ __forceinline__ void run(const float (&v)[64],
                                               float* __restrict__ outp) {
        outp[(size_t)C * DIM] = Tap<C, 0, false>::run(v, 0.f);
        WCol<C + 1, (C + 1 >= NROWS_W)>::run(v, outp);
    }
};
template<int C>
struct WCol<C, true> {
    static __device__ __forceinline__ void run(const float (&)[64], float*) {}
};

template<int GBASE, int RCNT, int WS, int R, bool Done>
struct HRow {
    static __device__ __forceinline__ void run(const float (&v)[64],
                                               float* __restrict__ outp) {
        outp[(size_t)(R * WS) * DIM] = Tap<GBASE + R, 0, false>::run(v, 0.f);
        HRow<GBASE, RCNT, WS, R + 1, (R + 1 >= RCNT)>::run(v, outp);
    }
};
template<int GBASE, int RCNT, int WS, int R>
struct HRow<GBASE, RCNT, WS, R, true> {
    static __device__ __forceinline__ void run(const float (&)[64], float*) {}
};

// ---------------------------------------------------------------------------
// Kernel 1 (W-pass): tmpW[i][c][d] = sum_k W[c][k] * weight[i][st_c+k][d]
// Block = (input row i, 128-float d-chunk). Data register-resident.
// ---------------------------------------------------------------------------
__global__ __launch_bounds__(128) void passW_kernel(const float* __restrict__ weight) {
    int i  = blockIdx.x;
    int d0 = blockIdx.y * 128;
    int tid = threadIdx.x;

    float v[64];
    const float* wrow = weight + (size_t)(i * 64) * DIM + d0 + tid;
    #pragma unroll
    for (int j = 0; j < 64; j++)
        v[j] = wrow[(size_t)j * DIM];

    float* outp = g_tmpW + (size_t)i * NROWS_W * DIM + d0 + tid;
    WCol<0, false>::run(v, outp);
}

// ---------------------------------------------------------------------------
// Kernel 2 (H-pass): pe2d[row(s,r,c)][d] = sum_k W[r][k] * tmpW[st_r+k][c][d]
// Block = (global resized column c, d-chunk). Data register-resident.
// ---------------------------------------------------------------------------
__global__ __launch_bounds__(128) void passH_kernel() {
    int c  = blockIdx.x;
    int d0 = blockIdx.y * 128;
    int tid = threadIdx.x;

    float v[64];
    const float* src = g_tmpW + (size_t)c * DIM + d0 + tid;
    #pragma unroll
    for (int i = 0; i < 64; i++)
        v[i] = src[(size_t)i * (NROWS_W * DIM)];

    if (c < 32) {
        float* outp = g_pe2d + (size_t)c * DIM + d0 + tid;
        HRow<0, 32, 32, 0, false>::run(v, outp);
    } else if (c < 48) {
        float* outp = g_pe2d + (size_t)(1024 + (c - 32)) * DIM + d0 + tid;
        HRow<32, 16, 16, 0, false>::run(v, outp);
    } else {
        float* outp = g_pe2d + (size_t)(1280 + (c - 48)) * DIM + d0 + tid;
        HRow<48, 48, 48, 0, false>::run(v, outp);
    }
}

// ---------------------------------------------------------------------------
// Kernel 3: out = x + pe(+tw). Block = 4 consecutive tokens x 320 threads.
// All sample boundaries and frame strides are multiples of 4, so sample,
// frame, and tw row are BLOCK-UNIFORM and pe rows are consecutive:
// decode once, reuse tw across 4 tokens, 4-deep MLP on the x stream.
// ---------------------------------------------------------------------------
__global__ __launch_bounds__(320) void add_kernel(const float4* __restrict__ x,
                                                  const float4* __restrict__ weight,
                                                  const float4* __restrict__ tw,
                                                  float4* __restrict__ out) {
    int t0 = blockIdx.x * TPB;
    int d4 = threadIdx.x;

    const float4* pe0;
    int frame;
    if (t0 < 8192) {                        // s0: t=8, 32x32
        frame = t0 >> 10;
        pe0 = (const float4*)g_pe2d + (size_t)(t0 & 1023) * D4;
    } else if (t0 < 12288) {                // s1: t=16, 16x16
        int u = t0 - 8192;
        frame = u >> 8;
        pe0 = (const float4*)g_pe2d + (size_t)(1024 + (u & 255)) * D4;
    } else if (t0 < 21504) {                // s2: t=4, 48x48
        int u = t0 - 12288;
        frame = u / 2304;
        pe0 = (const float4*)g_pe2d + (size_t)(1280 + (u - frame * 2304)) * D4;
    } else {                                // s3: t=1, identity 64x64
        frame = -1;
        pe0 = weight + (size_t)(t0 - 21504) * D4;
    }

    size_t base = (size_t)t0 * D4 + d4;

    float4 a[TPB], b[TPB];
    #pragma unroll
    for (int j = 0; j < TPB; j++) a[j] = __ldcs(&x[base + (size_t)j * D4]);
    #pragma unroll
    for (int j = 0; j < TPB; j++) b[j] = pe0[(size_t)j * D4 + d4];

    float4 t = make_float4(0.f, 0.f, 0.f, 0.f);
    if (frame >= 0) t = tw[(size_t)frame * D4 + d4];

    #pragma unroll
    for (int j = 0; j < TPB; j++) {
        float4 r;
        r.x = a[j].x + b[j].x + t.x;
        r.y = a[j].y + b[j].y + t.y;
        r.z = a[j].z + b[j].z + t.z;
        r.w = a[j].w + b[j].w + t.w;
        __stcs(&out[base + (size_t)j * D4], r);
    }
}

// ---------------------------------------------------------------------------
extern "C" void kernel_launch(void* const* d_in, const int* in_sizes, int n_in,
                              void* d_out, int out_size) {
    const float* x      = (const float*)d_in[0];
    const float* weight = (const float*)d_in[1];
    const float* tw     = (const float*)d_in[2];
    float* out = (float*)d_out;

    passW_kernel<<<dim3(64, 10), 128>>>(weight);
    passH_kernel<<<dim3(96, 10), 128>>>();
    add_kernel<<<TOKENS / TPB, 320>>>((const float4*)x, (const float4*)weight,
                                      (const float4*)tw, (float4*)out);
}